// round 3
// baseline (speedup 1.0000x reference)
#include <cuda_runtime.h>
#include <cstdint>

// Problem constants
#define MAX_NODES 100000
#define MAX_EDGES 1600000
#define ZD 128
#define ZD4 (ZD/4)           // 32 float4 per node row

#define SCAN_TPB 1024
#define MAX_SCAN_BLOCKS ((MAX_NODES + SCAN_TPB - 1) / SCAN_TPB)   // 98

// ---------------------------------------------------------------------------
// Scratch (__device__ globals; no cudaMalloc allowed)
// ---------------------------------------------------------------------------
__device__ float g_proj_src[MAX_NODES];
__device__ float g_proj_dst[MAX_NODES];
__device__ int   g_counts[MAX_NODES];
__device__ int   g_offsets[MAX_NODES];
__device__ int   g_cursor[MAX_NODES];
__device__ int   g_blocksums[MAX_SCAN_BLOCKS];
__device__ int   g_blockoffs[MAX_SCAN_BLOCKS];
__device__ int2  g_edges[MAX_EDGES];   // .x = src node, .y = float bits of exp(selu(e))

// SELU constants (match jax.nn.selu)
#define SELU_SCALE 1.0507009873554805f
#define SELU_SCALE_ALPHA 1.7580993408473766f

__device__ __forceinline__ int warp_incl_scan(int v, int lane) {
    #pragma unroll
    for (int o = 1; o < 32; o <<= 1) {
        int t = __shfl_up_sync(0xFFFFFFFFu, v, o);
        if (lane >= o) v += t;
    }
    return v;
}

// ---------------------------------------------------------------------------
// K0: projections (warp per node) + fused zeroing of per-node counts
// ---------------------------------------------------------------------------
__global__ void proj_kernel(const float* __restrict__ z,
                            const float* __restrict__ w,
                            int n_nodes) {
    int gtid  = blockIdx.x * blockDim.x + threadIdx.x;
    if (gtid < n_nodes) g_counts[gtid] = 0;          // fused init

    int gwarp = gtid >> 5;
    int lane  = threadIdx.x & 31;
    if (gwarp >= n_nodes) return;

    float4 zv = __ldg(((const float4*)(z + (size_t)gwarp * ZD)) + lane);
    float4 w1 = __ldg(((const float4*)w) + lane);
    float4 w2 = __ldg(((const float4*)w) + lane + 32);

    float s1 = zv.x * w1.x + zv.y * w1.y + zv.z * w1.z + zv.w * w1.w;
    float s2 = zv.x * w2.x + zv.y * w2.y + zv.z * w2.z + zv.w * w2.w;

    #pragma unroll
    for (int o = 16; o > 0; o >>= 1) {
        s1 += __shfl_xor_sync(0xFFFFFFFFu, s1, o);
        s2 += __shfl_xor_sync(0xFFFFFFFFu, s2, o);
    }
    if (lane == 0) {
        g_proj_src[gwarp] = s1;
        g_proj_dst[gwarp] = s2;
    }
}

// ---------------------------------------------------------------------------
// K1: histogram of dst (4 edges per thread via int4)
// ---------------------------------------------------------------------------
__global__ void hist_kernel(const int* __restrict__ dst, int n_edges) {
    int t  = blockIdx.x * blockDim.x + threadIdx.x;
    int e4 = n_edges >> 2;
    if (t < e4) {
        int4 d = __ldg(((const int4*)dst) + t);
        atomicAdd(&g_counts[d.x], 1);
        atomicAdd(&g_counts[d.y], 1);
        atomicAdd(&g_counts[d.z], 1);
        atomicAdd(&g_counts[d.w], 1);
    }
    // tail
    int e = e4 * 4 + t;
    if (t < (n_edges & 3) && e < n_edges) {
        atomicAdd(&g_counts[__ldg(dst + e)], 1);
    }
}

// ---------------------------------------------------------------------------
// K2a/b/c: exclusive scan (warp-shuffle based)
// ---------------------------------------------------------------------------
__global__ void scan1_kernel(int n) {
    __shared__ int wsum[32];
    int tid  = threadIdx.x;
    int lane = tid & 31;
    int wid  = tid >> 5;
    int i    = blockIdx.x * SCAN_TPB + tid;

    int v   = (i < n) ? g_counts[i] : 0;
    int inc = warp_incl_scan(v, lane);
    if (lane == 31) wsum[wid] = inc;
    __syncthreads();
    if (wid == 0) {
        int s  = wsum[lane];
        int si = warp_incl_scan(s, lane);
        if (lane == 31) g_blocksums[blockIdx.x] = si;   // block total
        wsum[lane] = si - s;                            // exclusive warp offset
    }
    __syncthreads();
    if (i < n) g_offsets[i] = inc - v + wsum[wid];
}

__global__ void scan2_kernel(int nblocks) {
    __shared__ int wsum[32];
    int lane = threadIdx.x & 31;
    int wid  = threadIdx.x >> 5;

    int v   = (threadIdx.x < nblocks) ? g_blocksums[threadIdx.x] : 0;
    int inc = warp_incl_scan(v, lane);
    if (lane == 31) wsum[wid] = inc;
    __syncthreads();
    if (wid == 0) {
        int s  = (lane < 4) ? wsum[lane] : 0;
        int si = warp_incl_scan(s, lane);
        wsum[lane] = si - s;
    }
    __syncthreads();
    if (threadIdx.x < nblocks) g_blockoffs[threadIdx.x] = inc - v + wsum[wid];
}

__global__ void scan3_kernel(int n) {
    int i = blockIdx.x * SCAN_TPB + threadIdx.x;
    if (i < n) {
        int o = g_offsets[i] + g_blockoffs[blockIdx.x];
        g_offsets[i] = o;
        g_cursor[i]  = o;
    }
}

// ---------------------------------------------------------------------------
// K3: scatter edges into CSR slots, computing softmax weight on the fly.
//     (selu output bounded -> exp cannot overflow fp32, segment-max dropped)
//     4 edges per thread via int4.
// ---------------------------------------------------------------------------
__device__ __forceinline__ void scatter_one(int s, int d) {
    float x  = g_proj_src[s] + g_proj_dst[d];
    float ee = (x > 0.f) ? (SELU_SCALE * x)
                         : (SELU_SCALE_ALPHA * (__expf(x) - 1.0f));
    float wgt = __expf(ee);
    int pos = atomicAdd(&g_cursor[d], 1);
    g_edges[pos] = make_int2(s, __float_as_int(wgt));
}

__global__ void scatter_kernel(const int* __restrict__ src,
                               const int* __restrict__ dst,
                               int n_edges) {
    int t  = blockIdx.x * blockDim.x + threadIdx.x;
    int e4 = n_edges >> 2;
    if (t < e4) {
        int4 s = __ldg(((const int4*)src) + t);
        int4 d = __ldg(((const int4*)dst) + t);
        scatter_one(s.x, d.x);
        scatter_one(s.y, d.y);
        scatter_one(s.z, d.z);
        scatter_one(s.w, d.w);
    }
    int e = e4 * 4 + t;
    if (t < (n_edges & 3) && e < n_edges) {
        scatter_one(__ldg(src + e), __ldg(dst + e));
    }
}

// ---------------------------------------------------------------------------
// K4: aggregate. Warp per node, register accumulation, 4-way unroll.
// ---------------------------------------------------------------------------
__global__ void agg_kernel(const float* __restrict__ z,
                           float* __restrict__ out,
                           int n_nodes) {
    int node = (blockIdx.x * blockDim.x + threadIdx.x) >> 5;
    int lane = threadIdx.x & 31;
    if (node >= n_nodes) return;

    const float4* z4 = (const float4*)z;
    size_t orow = (size_t)node * ZD4 + lane;

    int cnt = g_counts[node];
    if (cnt == 0) {                        // no incoming edges: pass through z
        ((float4*)out)[orow] = __ldg(&z4[orow]);
        return;
    }
    int beg = g_offsets[node];

    float4 acc = make_float4(0.f, 0.f, 0.f, 0.f);
    float  den = 0.f;

    int j = 0;
    for (; j + 4 <= cnt; j += 4) {
        int2 e0 = g_edges[beg + j];
        int2 e1 = g_edges[beg + j + 1];
        int2 e2 = g_edges[beg + j + 2];
        int2 e3 = g_edges[beg + j + 3];
        float w0 = __int_as_float(e0.y), w1 = __int_as_float(e1.y);
        float w2 = __int_as_float(e2.y), w3 = __int_as_float(e3.y);
        float4 z0 = __ldg(&z4[(size_t)e0.x * ZD4 + lane]);
        float4 z1 = __ldg(&z4[(size_t)e1.x * ZD4 + lane]);
        float4 z2 = __ldg(&z4[(size_t)e2.x * ZD4 + lane]);
        float4 z3 = __ldg(&z4[(size_t)e3.x * ZD4 + lane]);
        den += (w0 + w1) + (w2 + w3);
        acc.x += w0 * z0.x + w1 * z1.x + w2 * z2.x + w3 * z3.x;
        acc.y += w0 * z0.y + w1 * z1.y + w2 * z2.y + w3 * z3.y;
        acc.z += w0 * z0.z + w1 * z1.z + w2 * z2.z + w3 * z3.z;
        acc.w += w0 * z0.w + w1 * z1.w + w2 * z2.w + w3 * z3.w;
    }
    for (; j < cnt; j++) {
        int2 e0 = g_edges[beg + j];
        float w0 = __int_as_float(e0.y);
        float4 z0 = __ldg(&z4[(size_t)e0.x * ZD4 + lane]);
        den += w0;
        acc.x += w0 * z0.x; acc.y += w0 * z0.y;
        acc.z += w0 * z0.z; acc.w += w0 * z0.w;
    }

    float inv = 1.0f / den;
    ((float4*)out)[orow] = make_float4(acc.x * inv, acc.y * inv,
                                       acc.z * inv, acc.w * inv);
}

// ---------------------------------------------------------------------------
// Entry point. Inputs: z[f32 N*128], w[f32 256], src[i32 E], dst[i32 E].
// ---------------------------------------------------------------------------
extern "C" void kernel_launch(void* const* d_in, const int* in_sizes, int n_in,
                              void* d_out, int out_size) {
    const float* z   = (const float*)d_in[0];
    const float* w   = (const float*)d_in[1];
    const int*   src = (const int*)  d_in[2];
    const int*   dst = (const int*)  d_in[3];
    float*       out = (float*)      d_out;

    int n_nodes = in_sizes[0] / ZD;
    int n_edges = in_sizes[2];
    if (n_nodes > MAX_NODES) n_nodes = MAX_NODES;
    if (n_edges > MAX_EDGES) n_edges = MAX_EDGES;

    const int TPB = 256;
    int scan_blocks = (n_nodes + SCAN_TPB - 1) / SCAN_TPB;

    // K0: projections + zero counts
    long long proj_threads = (long long)n_nodes * 32;
    proj_kernel<<<(int)((proj_threads + TPB - 1) / TPB), TPB>>>(z, w, n_nodes);

    // K1: histogram (4 edges/thread)
    int hist_threads = (n_edges + 3) / 4 + 4;
    hist_kernel<<<(hist_threads + TPB - 1) / TPB, TPB>>>(dst, n_edges);

    // K2: scan
    scan1_kernel<<<scan_blocks, SCAN_TPB>>>(n_nodes);
    scan2_kernel<<<1, 128>>>(scan_blocks);
    scan3_kernel<<<scan_blocks, SCAN_TPB>>>(n_nodes);

    // K3: scatter (4 edges/thread)
    scatter_kernel<<<(hist_threads + TPB - 1) / TPB, TPB>>>(src, dst, n_edges);

    // K4: aggregate
    long long agg_threads = (long long)n_nodes * 32;
    agg_kernel<<<(int)((agg_threads + TPB - 1) / TPB), TPB>>>(z, out, n_nodes);
}

// round 5
// speedup vs baseline: 1.1358x; 1.1358x over previous
#include <cuda_runtime.h>
#include <cuda_fp16.h>
#include <cstdint>

// Problem constants
#define MAX_NODES 100000
#define MAX_EDGES 1600000
#define ZD 128
#define ZD4 (ZD/4)

#define SCAN_TPB 1024
#define MAX_SCAN_BLOCKS ((MAX_NODES + SCAN_TPB - 1) / SCAN_TPB)   // 98

// ---------------------------------------------------------------------------
// Scratch (__device__ globals; no cudaMalloc allowed)
// ---------------------------------------------------------------------------
__device__ float  g_proj_src[MAX_NODES];
__device__ float  g_proj_dst[MAX_NODES];
__device__ int    g_counts[MAX_NODES];
__device__ int    g_offsets[MAX_NODES];
__device__ int    g_cursor[MAX_NODES];
__device__ __half g_zh[(size_t)MAX_NODES * ZD];          // z compressed to fp16 (25.6 MB)
__device__ int2   g_edges[MAX_EDGES];                    // .x=src, .y=bits of exp(selu(e))
__device__ unsigned long long g_scan_state[MAX_SCAN_BLOCKS];  // status<<32 | value

// SELU constants (match jax.nn.selu)
#define SELU_SCALE 1.0507009873554805f
#define SELU_SCALE_ALPHA 1.7580993408473766f

__device__ __forceinline__ int warp_incl_scan(int v, int lane) {
    #pragma unroll
    for (int o = 1; o < 32; o <<= 1) {
        int t = __shfl_up_sync(0xFFFFFFFFu, v, o);
        if (lane >= o) v += t;
    }
    return v;
}

// ---------------------------------------------------------------------------
// K0: projections (warp per node) + z->fp16 conversion + scratch re-init.
// ---------------------------------------------------------------------------
__global__ void proj_kernel(const float* __restrict__ z,
                            const float* __restrict__ w,
                            int n_nodes) {
    int gtid = blockIdx.x * blockDim.x + threadIdx.x;
    if (gtid < n_nodes) g_counts[gtid] = 0;
    if (gtid < MAX_SCAN_BLOCKS) g_scan_state[gtid] = 0ull;

    int gwarp = gtid >> 5;
    int lane  = threadIdx.x & 31;
    if (gwarp >= n_nodes) return;

    float4 zv = __ldg(((const float4*)(z + (size_t)gwarp * ZD)) + lane);
    float4 w1 = __ldg(((const float4*)w) + lane);
    float4 w2 = __ldg(((const float4*)w) + lane + 32);

    // fp16 copy of this node's row (lane covers dims [4*lane, 4*lane+4))
    __half2 h0 = __floats2half2_rn(zv.x, zv.y);
    __half2 h1 = __floats2half2_rn(zv.z, zv.w);
    uint2 packed;
    packed.x = *reinterpret_cast<unsigned int*>(&h0);
    packed.y = *reinterpret_cast<unsigned int*>(&h1);
    ((uint2*)g_zh)[(size_t)gwarp * 32 + lane] = packed;

    float s1 = zv.x * w1.x + zv.y * w1.y + zv.z * w1.z + zv.w * w1.w;
    float s2 = zv.x * w2.x + zv.y * w2.y + zv.z * w2.z + zv.w * w2.w;

    #pragma unroll
    for (int o = 16; o > 0; o >>= 1) {
        s1 += __shfl_xor_sync(0xFFFFFFFFu, s1, o);
        s2 += __shfl_xor_sync(0xFFFFFFFFu, s2, o);
    }
    if (lane == 0) {
        g_proj_src[gwarp] = s1;
        g_proj_dst[gwarp] = s2;
    }
}

// ---------------------------------------------------------------------------
// K1: histogram of dst (scalar: 1 edge per thread)
// ---------------------------------------------------------------------------
__global__ void hist_kernel(const int* __restrict__ dst, int n_edges) {
    int e = blockIdx.x * blockDim.x + threadIdx.x;
    if (e < n_edges) atomicAdd(&g_counts[__ldg(dst + e)], 1);
}

// ---------------------------------------------------------------------------
// K2: single-pass exclusive scan (decoupled lookback). Writes offsets+cursor.
// status: 0 = invalid, 1 = aggregate ready, 2 = inclusive prefix ready.
// Grid (98 blocks) is fully resident in one wave on 148 SMs, so lookback
// always terminates; __nanosleep backoff guarantees progress regardless.
// ---------------------------------------------------------------------------
__global__ void scan_kernel(int n) {
    __shared__ int wsum[32];
    __shared__ int sh_total;
    __shared__ int sh_exp;

    int bid  = blockIdx.x;
    int lane = threadIdx.x & 31;
    int wid  = threadIdx.x >> 5;
    int i    = bid * SCAN_TPB + threadIdx.x;

    int v   = (i < n) ? g_counts[i] : 0;
    int inc = warp_incl_scan(v, lane);
    if (lane == 31) wsum[wid] = inc;
    __syncthreads();

    if (wid == 0) {
        int s  = wsum[lane];
        int si = warp_incl_scan(s, lane);
        wsum[lane] = si - s;
        if (lane == 31) {
            sh_total = si;
            unsigned long long st =
                (((bid == 0) ? 2ull : 1ull) << 32) | (unsigned int)si;
            atomicExch(&g_scan_state[bid], st);
        }
    }
    __syncthreads();
    int ex_in_block = inc - v + wsum[wid];

    // warp 0: lookback for the exclusive prefix of this block
    if (wid == 0) {
        int expfx = 0;
        if (bid > 0) {
            int j = bid - 1;
            while (true) {
                int idx = j - lane;
                unsigned long long s = (idx >= 0)
                    ? atomicAdd(&g_scan_state[idx], 0ull)
                    : (2ull << 32);                      // OOB => prefix 0
                int st = (int)(s >> 32);
                if (__any_sync(0xFFFFFFFFu, st == 0)) {  // predecessor not ready
                    __nanosleep(20);
                    continue;
                }
                int val = (int)(s & 0xFFFFFFFFull);
                unsigned pm = __ballot_sync(0xFFFFFFFFu, st == 2);
                if (pm) {
                    int plane = __ffs(pm) - 1;           // nearest full prefix
                    int c = (lane <= plane) ? val : 0;
                    #pragma unroll
                    for (int o = 16; o > 0; o >>= 1)
                        c += __shfl_xor_sync(0xFFFFFFFFu, c, o);
                    expfx += c;
                    break;
                } else {                                 // 32 aggregates
                    int c = val;
                    #pragma unroll
                    for (int o = 16; o > 0; o >>= 1)
                        c += __shfl_xor_sync(0xFFFFFFFFu, c, o);
                    expfx += c;
                    j -= 32;
                }
            }
        }
        if (lane == 0) {
            sh_exp = expfx;
            atomicExch(&g_scan_state[bid],
                       (2ull << 32) | (unsigned int)(expfx + sh_total));
        }
    }
    __syncthreads();

    if (i < n) {
        int off = sh_exp + ex_in_block;
        g_offsets[i] = off;
        g_cursor[i]  = off;
    }
}

// ---------------------------------------------------------------------------
// K3: scatter edges into CSR slots with softmax weight computed on the fly.
//     (selu output bounded -> exp cannot overflow fp32; segment-max dropped)
// ---------------------------------------------------------------------------
__global__ void scatter_kernel(const int* __restrict__ src,
                               const int* __restrict__ dst,
                               int n_edges) {
    int e = blockIdx.x * blockDim.x + threadIdx.x;
    if (e >= n_edges) return;

    int s = __ldg(src + e);
    int d = __ldg(dst + e);

    float x  = g_proj_src[s] + g_proj_dst[d];
    float ee = (x > 0.f) ? (SELU_SCALE * x)
                         : (SELU_SCALE_ALPHA * (__expf(x) - 1.0f));
    float wgt = __expf(ee);

    int pos = atomicAdd(&g_cursor[d], 1);
    g_edges[pos] = make_int2(s, __float_as_int(wgt));
}

// ---------------------------------------------------------------------------
// K4: aggregate. HALF-WARP (16 lanes) per node over the fp16 z copy.
//     Lane covers dims [8l, 8l+8): one uint4 (16 B = 8 halfs) per edge.
//     den is lane-redundant scalar math (no reduction needed).
// ---------------------------------------------------------------------------
__global__ void agg_kernel(const float* __restrict__ z,
                           float* __restrict__ out,
                           int n_nodes) {
    int t    = blockIdx.x * blockDim.x + threadIdx.x;
    int node = t >> 4;
    int l    = t & 15;
    if (node >= n_nodes) return;

    size_t ob = (size_t)node * ZD4 + l * 2;          // two float4 slots

    int cnt = g_counts[node];
    if (cnt == 0) {                                  // deg-0: exact passthrough
        const float4* z4 = (const float4*)z;
        ((float4*)out)[ob]     = __ldg(&z4[ob]);
        ((float4*)out)[ob + 1] = __ldg(&z4[ob + 1]);
        return;
    }
    int beg = g_offsets[node];

    const uint4* zh = (const uint4*)g_zh;            // 16 uint4 per row
    const int2*  eg = (const int2*)g_edges;

    float acc[8] = {0.f, 0.f, 0.f, 0.f, 0.f, 0.f, 0.f, 0.f};
    float den = 0.f;

    int j = 0;
    for (; j + 2 <= cnt; j += 2) {
        int2 e0 = __ldg(&eg[beg + j]);
        int2 e1 = __ldg(&eg[beg + j + 1]);
        float w0 = __int_as_float(e0.y);
        float w1 = __int_as_float(e1.y);
        uint4 v0 = __ldg(&zh[(size_t)e0.x * 16 + l]);
        uint4 v1 = __ldg(&zh[(size_t)e1.x * 16 + l]);
        den += w0 + w1;
        {
            const __half2* h = (const __half2*)&v0;
            #pragma unroll
            for (int k = 0; k < 4; k++) {
                float2 f = __half22float2(h[k]);
                acc[2*k]   += w0 * f.x;
                acc[2*k+1] += w0 * f.y;
            }
        }
        {
            const __half2* h = (const __half2*)&v1;
            #pragma unroll
            for (int k = 0; k < 4; k++) {
                float2 f = __half22float2(h[k]);
                acc[2*k]   += w1 * f.x;
                acc[2*k+1] += w1 * f.y;
            }
        }
    }
    if (j < cnt) {
        int2 e0 = __ldg(&eg[beg + j]);
        float w0 = __int_as_float(e0.y);
        uint4 v0 = __ldg(&zh[(size_t)e0.x * 16 + l]);
        den += w0;
        const __half2* h = (const __half2*)&v0;
        #pragma unroll
        for (int k = 0; k < 4; k++) {
            float2 f = __half22float2(h[k]);
            acc[2*k]   += w0 * f.x;
            acc[2*k+1] += w0 * f.y;
        }
    }

    float inv = 1.0f / den;
    ((float4*)out)[ob]     = make_float4(acc[0]*inv, acc[1]*inv, acc[2]*inv, acc[3]*inv);
    ((float4*)out)[ob + 1] = make_float4(acc[4]*inv, acc[5]*inv, acc[6]*inv, acc[7]*inv);
}

// ---------------------------------------------------------------------------
// Entry point. Inputs: z[f32 N*128], w[f32 256], src[i32 E], dst[i32 E].
// ---------------------------------------------------------------------------
extern "C" void kernel_launch(void* const* d_in, const int* in_sizes, int n_in,
                              void* d_out, int out_size) {
    const float* z   = (const float*)d_in[0];
    const float* w   = (const float*)d_in[1];
    const int*   src = (const int*)  d_in[2];
    const int*   dst = (const int*)  d_in[3];
    float*       out = (float*)      d_out;

    int n_nodes = in_sizes[0] / ZD;
    int n_edges = in_sizes[2];
    if (n_nodes > MAX_NODES) n_nodes = MAX_NODES;
    if (n_edges > MAX_EDGES) n_edges = MAX_EDGES;

    const int TPB = 256;
    int scan_blocks = (n_nodes + SCAN_TPB - 1) / SCAN_TPB;

    // K0: projections + fp16 conversion + scratch re-init
    long long proj_threads = (long long)n_nodes * 32;
    proj_kernel<<<(int)((proj_threads + TPB - 1) / TPB), TPB>>>(z, w, n_nodes);

    // K1: histogram
    hist_kernel<<<(n_edges + TPB - 1) / TPB, TPB>>>(dst, n_edges);

    // K2: single-pass scan
    scan_kernel<<<scan_blocks, SCAN_TPB>>>(n_nodes);

    // K3: scatter
    scatter_kernel<<<(n_edges + TPB - 1) / TPB, TPB>>>(src, dst, n_edges);

    // K4: aggregate (half-warp per node)
    long long agg_threads = (long long)n_nodes * 16;
    agg_kernel<<<(int)((agg_threads + TPB - 1) / TPB), TPB>>>(z, out, n_nodes);
}